// round 15
// baseline (speedup 1.0000x reference)
#include <cuda_runtime.h>
#include <math.h>

// Problem constants
#define KEDGE   16
#define SDIM    8
#define HHEAD   4
#define FDIM    576
#define FPH     144
#define NNODES  8192

// Tiling: 8 nodes (128 edges) per block, 4 warps, warp = 32 edges = 2 m16 atoms
#define GN      8
#define EPB     128
#define THREADS 128
#define XSTR    68    // xs row stride (f32)

// smem offsets (u32 units)
// act: warp w -> u32 [w*2048, (w+1)*2048); atom m at +m*1024 (hi 512, lo 512)
#define OFF_ACT 0                       // 8192 u32 (32 KB)
#define OFF_WR  8192                    // W ring: 2 slots x 4096 u32 (2 x 16 KB)
#define OFF_XS  16384                   // [128][68] f32 = 8704
#define OFF_QN  25088                   // [8][64]
#define OFF_LG  25600                   // [128][4]
#define OFF_AL  26112                   // [128][4]
#define OFF_CW  26624                   // [128]
#define SMEM_U32 26752                  // 107008 B -> 2 CTAs/SM

// node accumulators in global scratch (fully rewritten every launch)
__device__ float g_accN[NNODES * FDIM];

// ---- fragment-ordered packed weights: uint4 {b0h, b1h, b0l, b1l} ----
#define Q_K1 0          // 64x64 -> 1024 uint4 (16 KB)
#define Q_K2 1024
#define Q_V1 2048
#define Q_V2 3072
#define Q_K3 4096       // 64x576 -> 9216 uint4 (9 chunks x 1024)
#define Q_V3 13312
#define Q_TOTAL 22528
__device__ __align__(16) uint4 g_Wpk[Q_TOTAL];

__device__ __forceinline__ unsigned pack_bf16x2(float v_odd, float v_even) {
    unsigned r;
    asm("cvt.rn.bf16x2.f32 %0, %1, %2;" : "=r"(r) : "f"(v_odd), "f"(v_even));
    return r;
}
__device__ __forceinline__ float bf_lo_f(unsigned u) { return __uint_as_float(u << 16); }
__device__ __forceinline__ float bf_hi_f(unsigned u) { return __uint_as_float(u & 0xffff0000u); }

__device__ __forceinline__ void mma16(float c[4], const unsigned a[4],
                                      unsigned b0, unsigned b1) {
    asm("mma.sync.aligned.m16n8k16.row.col.f32.bf16.bf16.f32 "
        "{%0,%1,%2,%3}, {%4,%5,%6,%7}, {%8,%9}, {%0,%1,%2,%3};"
        : "+f"(c[0]), "+f"(c[1]), "+f"(c[2]), "+f"(c[3])
        : "r"(a[0]), "r"(a[1]), "r"(a[2]), "r"(a[3]), "r"(b0), "r"(b1));
}

__device__ __forceinline__ float gelu_f(float x) {
    float u = 0.7978845608028654f * (x + 0.044715f * x * x * x);
    float t;
    asm("tanh.approx.f32 %0, %1;" : "=f"(t) : "f"(u));
    return 0.5f * x * (1.0f + t);
}

__device__ __forceinline__ void cp16(unsigned saddr, const void* gptr) {
    asm volatile("cp.async.cg.shared.global [%0], [%1], 16;"
                 :: "r"(saddr), "l"(gptr) : "memory");
}
#define CP_COMMIT() asm volatile("cp.async.commit_group;" ::: "memory")
#define CP_WAIT(n)  asm volatile("cp.async.wait_group %0;" :: "n"(n) : "memory")

__global__ void prep_kernel(const float* __restrict__ Wk1, const float* __restrict__ Wk2,
                            const float* __restrict__ Wk3, const float* __restrict__ Wv1,
                            const float* __restrict__ Wv2, const float* __restrict__ Wv3) {
    int i = blockIdx.x * 256 + threadIdx.x;
    if (i >= Q_TOTAL) return;
    const float* src; int ncols, q;
    if      (i < Q_K2) { src = Wk1; ncols = 64;  q = i - Q_K1; }
    else if (i < Q_V1) { src = Wk2; ncols = 64;  q = i - Q_K2; }
    else if (i < Q_V2) { src = Wv1; ncols = 64;  q = i - Q_V1; }
    else if (i < Q_K3) { src = Wv2; ncols = 64;  q = i - Q_V2; }
    else if (i < Q_V3) { src = Wk3; ncols = 576; q = i - Q_K3; }
    else               { src = Wv3; ncols = 576; q = i - Q_V3; }
    const int jblk = q >> 7;
    const int kb   = (q >> 5) & 3;
    const int lane = q & 31;
    const int gr   = lane >> 2;
    const int tig  = lane & 3;
    const int n    = jblk * 8 + gr;
    const int kA   = 2 * (kb * 8 + tig);
    const int kB   = 2 * (kb * 8 + tig + 4);
    float a0 = src[kA * ncols + n],       a1 = src[(kA + 1) * ncols + n];
    float b0 = src[kB * ncols + n],       b1 = src[(kB + 1) * ncols + n];
    unsigned h0 = pack_bf16x2(a1, a0);
    unsigned h1 = pack_bf16x2(b1, b0);
    unsigned l0 = pack_bf16x2(a1 - bf_hi_f(h0), a0 - bf_lo_f(h0));
    unsigned l1 = pack_bf16x2(b1 - bf_hi_f(h1), b0 - bf_lo_f(h1));
    uint4 o; o.x = h0; o.y = h1; o.z = l0; o.w = l1;
    g_Wpk[i] = o;
}

// write one (c2) column-pair for an edge into its atom's fragment-quad layout
__device__ __forceinline__ void act_store_c2(unsigned* hw, unsigned* lw,
                                             int c2, int gr_e, int gr8,
                                             float v0, float v1) {
    unsigned h = pack_bf16x2(v1, v0);
    unsigned l = pack_bf16x2(v1 - bf_hi_f(h), v0 - bf_lo_f(h));
    const int quad = ((c2 >> 3) * 4 + (c2 & 3)) * 8 + gr_e;
    const int idx  = quad * 4 + ((c2 >> 2) & 1) * 2 + gr8;
    hw[idx] = h;
    lw[idx] = l;
}

// 32x64x64 layer GEMM (2 atoms); W from smem slot; in-place gelu+split store.
__device__ __forceinline__ void layer_gemm(uint4* actq, const uint4* __restrict__ Wq,
                                           int gr, int tig, int lane) {
    float acc[2][8][4];
#pragma unroll
    for (int m = 0; m < 2; m++)
#pragma unroll
        for (int j = 0; j < 8; j++)
#pragma unroll
            for (int p = 0; p < 4; p++) acc[m][j][p] = 0.f;

#pragma unroll
    for (int kb = 0; kb < 4; kb++) {
        const int qi = (kb * 4 + tig) * 8 + gr;
        uint4 ah0 = actq[qi],        al0 = actq[128 + qi];
        uint4 ah1 = actq[256 + qi],  al1 = actq[384 + qi];
        unsigned Ah[2][4] = {{ah0.x, ah0.y, ah0.z, ah0.w}, {ah1.x, ah1.y, ah1.z, ah1.w}};
        unsigned Al[2][4] = {{al0.x, al0.y, al0.z, al0.w}, {al1.x, al1.y, al1.z, al1.w}};
        const uint4* wp = Wq + kb * 32 + lane;
#pragma unroll
        for (int j = 0; j < 8; j++) {
            uint4 w = wp[j * 128];
#pragma unroll
            for (int m = 0; m < 2; m++) {
                mma16(acc[m][j], Ah[m], w.x, w.y);
                mma16(acc[m][j], Al[m], w.x, w.y);
                mma16(acc[m][j], Ah[m], w.z, w.w);
            }
        }
    }
    __syncwarp();
#pragma unroll
    for (int m = 0; m < 2; m++) {
        unsigned* hw = (unsigned*)actq + m * 1024;
        unsigned* lw = hw + 512;
#pragma unroll
        for (int j = 0; j < 8; j++) {
            float g0 = gelu_f(acc[m][j][0]), g1 = gelu_f(acc[m][j][1]);
            float g2 = gelu_f(acc[m][j][2]), g3 = gelu_f(acc[m][j][3]);
            unsigned hA = pack_bf16x2(g1, g0);
            unsigned hB = pack_bf16x2(g3, g2);
            unsigned lA = pack_bf16x2(g1 - bf_hi_f(hA), g0 - bf_lo_f(hA));
            unsigned lB = pack_bf16x2(g3 - bf_hi_f(hB), g2 - bf_lo_f(hB));
            const int c2   = j * 4 + tig;
            const int quad = ((c2 >> 3) * 4 + (c2 & 3)) * 8 + gr;
            const int base = quad * 4 + ((c2 >> 2) & 1) * 2;
            *reinterpret_cast<uint2*>(hw + base) = make_uint2(hA, hB);
            *reinterpret_cast<uint2*>(lw + base) = make_uint2(lA, lB);
        }
    }
    __syncwarp();
}

// 32x32 half-chunk; W from smem slot (1024 uint4 = one chunk); acc[2][4][4].
__device__ __forceinline__ void chunk_half(const uint4* actq, const uint4* __restrict__ Wq,
                                           int nh, int gr, int tig, int lane,
                                           float acc[2][4][4]) {
#pragma unroll
    for (int m = 0; m < 2; m++)
#pragma unroll
        for (int j = 0; j < 4; j++)
#pragma unroll
            for (int p = 0; p < 4; p++) acc[m][j][p] = 0.f;

#pragma unroll
    for (int kb = 0; kb < 4; kb++) {
        const int qi = (kb * 4 + tig) * 8 + gr;
        uint4 ah0 = actq[qi],        al0 = actq[128 + qi];
        uint4 ah1 = actq[256 + qi],  al1 = actq[384 + qi];
        unsigned Ah[2][4] = {{ah0.x, ah0.y, ah0.z, ah0.w}, {ah1.x, ah1.y, ah1.z, ah1.w}};
        unsigned Al[2][4] = {{al0.x, al0.y, al0.z, al0.w}, {al1.x, al1.y, al1.z, al1.w}};
        const uint4* wp = Wq + nh * 512 + kb * 32 + lane;
#pragma unroll
        for (int j = 0; j < 4; j++) {
            uint4 w = wp[j * 128];
#pragma unroll
            for (int m = 0; m < 2; m++) {
                mma16(acc[m][j], Ah[m], w.x, w.y);
                mma16(acc[m][j], Al[m], w.x, w.y);
                mma16(acc[m][j], Ah[m], w.z, w.w);
            }
        }
    }
}

__global__ __launch_bounds__(THREADS, 2)
void fused_attn_kernel(const float* __restrict__ node_feat,
                       const float* __restrict__ edge_sh,
                       const float* __restrict__ edge_inv,
                       const float* __restrict__ cutoff,
                       const float* __restrict__ W_logit,
                       const float* __restrict__ W_out,
                       const int* __restrict__ edge_src,
                       float* __restrict__ out) {
    extern __shared__ unsigned smu[];
    unsigned sbase;
    asm("{ .reg .u64 t; cvta.to.shared.u64 t, %1; cvt.u32.u64 %0, t; }"
        : "=r"(sbase) : "l"(smu));

    float* xs   = (float*)(smu + OFF_XS);
    float* qn   = (float*)(smu + OFF_QN);
    float* lg   = (float*)(smu + OFF_LG);
    float* al   = (float*)(smu + OFF_AL);
    float* cw   = (float*)(smu + OFF_CW);

    const int tid  = threadIdx.x;
    const int warp = tid >> 5;
    const int lane = tid & 31;
    const int gr   = lane >> 2;
    const int tig  = lane & 3;
    const int ew0  = warp * 32;
    const int n0   = blockIdx.x * GN;
    const int eg0  = blockIdx.x * EPB;

    uint4* actq = reinterpret_cast<uint4*>(smu + OFF_ACT) + warp * 512;
    const uint4* Wg = g_Wpk;

    // stage one 1024-uint4 (16 KB) image into a ring slot via cp.async
    auto stage = [&](int gbase, int slot) {
        unsigned dst = sbase + (OFF_WR + slot * 4096) * 4 + tid * 16;
        const uint4* src = Wg + gbase + tid;
#pragma unroll
        for (int i = 0; i < 8; i++)
            cp16(dst + i * 2048, src + i * 128);
    };
    auto slotp = [&](int slot) {
        return reinterpret_cast<const uint4*>(smu + OFF_WR + slot * 4096);
    };

    // ---------- phase 0 ----------
    cw[tid] = cutoff[eg0 + tid];
    for (int i = tid; i < GN * 64; i += THREADS) qn[i] = node_feat[n0 * 64 + i];
    {   // lane = one edge of this warp (32 edges)
        const int el = lane;
        const int m  = el >> 4;
        const int e16 = el & 15;
        const int gre = e16 & 7, gr8 = e16 >> 3;
        unsigned* hw_e = smu + OFF_ACT + warp * 2048 + m * 1024;
        unsigned* lw_e = hw_e + 512;
        const int e  = ew0 + el;
        const int ge = eg0 + e;
        const int srce = edge_src[ge];
#pragma unroll
        for (int m4 = 0; m4 < 16; m4++) {
            const int c4 = m4 * 4;
            float4 v = *reinterpret_cast<const float4*>(edge_inv + ge * 64 + c4);
            act_store_c2(hw_e, lw_e, (c4 >> 1),     gre, gr8, v.x, v.y);
            act_store_c2(hw_e, lw_e, (c4 >> 1) + 1, gre, gr8, v.z, v.w);
            *reinterpret_cast<float4*>(xs + e * XSTR + c4) =
                *reinterpret_cast<const float4*>(node_feat + srce * 64 + c4);
        }
    }

    // per-edge sh values for this thread's columns, straight from global
    float shv0[2][2], shv1[2][2];   // [m][A/B]
#pragma unroll
    for (int m = 0; m < 2; m++) {
        const int geA = eg0 + ew0 + 16 * m + gr;
        const int geB = geA + 8;
        float2 sA = *reinterpret_cast<const float2*>(edge_sh + geA * 8 + 2 * tig);
        float2 sB = *reinterpret_cast<const float2*>(edge_sh + geB * 8 + 2 * tig);
        shv0[m][0] = sA.x; shv1[m][0] = sA.y;
        shv0[m][1] = sB.x; shv1[m][1] = sB.y;
    }
    __syncthreads();

    // ---------- key MLP layers 1,2 (W staged into slot 0) ----------
    stage(Q_K1, 0); CP_COMMIT(); CP_WAIT(0); __syncthreads();
    layer_gemm(actq, slotp(0), gr, tig, lane);
    __syncthreads();
    stage(Q_K2, 0); CP_COMMIT(); CP_WAIT(0); __syncthreads();
    layer_gemm(actq, slotp(0), gr, tig, lane);
    __syncthreads();

    // ---------- key layer-3: 9 chunks, cp.async double-buffered ----------
    float pl[2][2][4];   // [m][A/B][h]
#pragma unroll
    for (int m = 0; m < 2; m++)
#pragma unroll
        for (int i = 0; i < 2; i++)
#pragma unroll
            for (int h = 0; h < 4; h++) pl[m][i][h] = 0.f;

    stage(Q_K3, 0); CP_COMMIT();
#pragma unroll 1
    for (int ci = 0; ci < 9; ci++) {
        if (ci < 8) { stage(Q_K3 + (ci + 1) * 1024, (ci + 1) & 1); CP_COMMIT(); CP_WAIT(1); }
        else        { CP_WAIT(0); }
        __syncthreads();   // slot ci&1 ready, visible to all warps
        const uint4* ws = slotp(ci & 1);

#pragma unroll 1
        for (int nh = 0; nh < 2; nh++) {
            const int s = ci * 2 + nh;
            float acc[2][4][4];
            chunk_half(actq, ws, nh, gr, tig, lane, acc);

            if (s < 2) {
#pragma unroll
                for (int j = 0; j < 4; j++) {
                    const int t0 = s * 32 + 8 * j + 2 * tig;
                    float4 wl0 = *reinterpret_cast<const float4*>(W_logit + t0 * 4);
                    float4 wl1 = *reinterpret_cast<const float4*>(W_logit + t0 * 4 + 4);
#pragma unroll
                    for (int m = 0; m < 2; m++) {
                        const float* qrow = qn + (2 * warp + m) * 64;
                        const float q0 = qrow[t0], q1 = qrow[t0 + 1];
                        const int eA = ew0 + 16 * m + gr, eB = eA + 8;
                        float cA0 = q0 * xs[eA * XSTR + t0]     * acc[m][j][0];
                        float cA1 = q1 * xs[eA * XSTR + t0 + 1] * acc[m][j][1];
                        float cB0 = q0 * xs[eB * XSTR + t0]     * acc[m][j][2];
                        float cB1 = q1 * xs[eB * XSTR + t0 + 1] * acc[m][j][3];
                        pl[m][0][0] += cA0 * wl0.x + cA1 * wl1.x;
                        pl[m][0][1] += cA0 * wl0.y + cA1 * wl1.y;
                        pl[m][0][2] += cA0 * wl0.z + cA1 * wl1.z;
                        pl[m][0][3] += cA0 * wl0.w + cA1 * wl1.w;
                        pl[m][1][0] += cB0 * wl0.x + cB1 * wl1.x;
                        pl[m][1][1] += cB0 * wl0.y + cB1 * wl1.y;
                        pl[m][1][2] += cB0 * wl0.z + cB1 * wl1.z;
                        pl[m][1][3] += cB0 * wl0.w + cB1 * wl1.w;
                    }
                }
            } else {
#pragma unroll
                for (int j = 0; j < 4; j++) {
                    const int d = 4 * s - 8 + j;
                    float4 wl = *reinterpret_cast<const float4*>(W_logit + (64 + d) * 4);
#pragma unroll
                    for (int m = 0; m < 2; m++) {
                        const float qd = qn[(2 * warp + m) * 64 + d];
                        const int eA = ew0 + 16 * m + gr, eB = eA + 8;
                        float cA = qd * xs[eA * XSTR + d] *
                                   (shv0[m][0] * shv0[m][0] * acc[m][j][0] +
                                    shv1[m][0] * shv1[m][0] * acc[m][j][1]);
                        float cB = qd * xs[eB * XSTR + d] *
                                   (shv0[m][1] * shv0[m][1] * acc[m][j][2] +
                                    shv1[m][1] * shv1[m][1] * acc[m][j][3]);
                        pl[m][0][0] += cA * wl.x; pl[m][0][1] += cA * wl.y;
                        pl[m][0][2] += cA * wl.z; pl[m][0][3] += cA * wl.w;
                        pl[m][1][0] += cB * wl.x; pl[m][1][1] += cB * wl.y;
                        pl[m][1][2] += cB * wl.z; pl[m][1][3] += cB * wl.w;
                    }
                }
            }
        }
        __syncthreads();   // all warps done with slot ci&1 before restaging
    }

    // reduce pl over the 4 tig lanes; tig==0 stores
#pragma unroll
    for (int msk = 1; msk < 4; msk <<= 1)
#pragma unroll
        for (int m = 0; m < 2; m++)
#pragma unroll
            for (int i = 0; i < 2; i++)
#pragma unroll
                for (int h = 0; h < 4; h++)
                    pl[m][i][h] += __shfl_xor_sync(0xffffffffu, pl[m][i][h], msk);
    if (tig == 0) {
#pragma unroll
        for (int m = 0; m < 2; m++) {
            const int eA = ew0 + 16 * m + gr, eB = eA + 8;
            *reinterpret_cast<float4*>(lg + eA * 4) =
                make_float4(pl[m][0][0], pl[m][0][1], pl[m][0][2], pl[m][0][3]);
            *reinterpret_cast<float4*>(lg + eB * 4) =
                make_float4(pl[m][1][0], pl[m][1][1], pl[m][1][2], pl[m][1][3]);
        }
    }
    __syncwarp();

    // reload edge_inv split into act (warp-local rows)
    {
        const int el = lane;
        const int m  = el >> 4;
        const int e16 = el & 15;
        const int gre = e16 & 7, gr8 = e16 >> 3;
        unsigned* hw_e = smu + OFF_ACT + warp * 2048 + m * 1024;
        unsigned* lw_e = hw_e + 512;
        const int ge = eg0 + ew0 + el;
#pragma unroll
        for (int m4 = 0; m4 < 16; m4++) {
            const int c4 = m4 * 4;
            float4 v = *reinterpret_cast<const float4*>(edge_inv + ge * 64 + c4);
            act_store_c2(hw_e, lw_e, (c4 >> 1),     gre, gr8, v.x, v.y);
            act_store_c2(hw_e, lw_e, (c4 >> 1) + 1, gre, gr8, v.z, v.w);
        }
    }
    __syncthreads();   // lg visible

    // ---------- softmax ----------
    if (tid < GN * HHEAD) {
        const int n = tid >> 2, h = tid & 3;
        float mx = -3.0e38f;
        for (int j = 0; j < KEDGE; j++)
            mx = fmaxf(mx, lg[(n * KEDGE + j) * 4 + h]);
        float z = 0.f;
        float ex[KEDGE];
        for (int j = 0; j < KEDGE; j++) {
            const int e = n * KEDGE + j;
            ex[j] = cw[e] * expf(lg[e * 4 + h] - mx);
            z += ex[j];
        }
        if (z == 0.f) z = 1.f;
        const float inv = 1.f / z;
        for (int j = 0; j < KEDGE; j++)
            al[(n * KEDGE + j) * 4 + h] = sqrtf(ex[j] * inv);
    }

    // ---------- value MLP layers 1,2 ----------
    __syncthreads();
    stage(Q_V1, 0); CP_COMMIT(); CP_WAIT(0); __syncthreads();
    layer_gemm(actq, slotp(0), gr, tig, lane);
    __syncthreads();
    stage(Q_V2, 0); CP_COMMIT(); CP_WAIT(0); __syncthreads();
    layer_gemm(actq, slotp(0), gr, tig, lane);
    __syncthreads();   // al also visible by now

    // ---------- value layer-3: 9 chunks, double-buffered -> g_accN ----------
    stage(Q_V3, 0); CP_COMMIT();
#pragma unroll 1
    for (int ci = 0; ci < 9; ci++) {
        if (ci < 8) { stage(Q_V3 + (ci + 1) * 1024, (ci + 1) & 1); CP_COMMIT(); CP_WAIT(1); }
        else        { CP_WAIT(0); }
        __syncthreads();
        const uint4* ws = slotp(ci & 1);

#pragma unroll 1
        for (int nh = 0; nh < 2; nh++) {
            const int s = ci * 2 + nh;
            float acc[2][4][4];
            chunk_half(actq, ws, nh, gr, tig, lane, acc);

            float pk[2][4][2];
            if (s < 2) {
#pragma unroll
                for (int m = 0; m < 2; m++) {
                    const int eA = ew0 + 16 * m + gr, eB = eA + 8;
                    const float aA = al[eA * 4], aB = al[eB * 4];
#pragma unroll
                    for (int j = 0; j < 4; j++) {
                        const int t0 = s * 32 + 8 * j + 2 * tig;
                        pk[m][j][0] = xs[eA * XSTR + t0]     * acc[m][j][0] * aA
                                    + xs[eB * XSTR + t0]     * acc[m][j][2] * aB;
                        pk[m][j][1] = xs[eA * XSTR + t0 + 1] * acc[m][j][1] * aA
                                    + xs[eB * XSTR + t0 + 1] * acc[m][j][3] * aB;
                    }
                }
            } else {
#pragma unroll
                for (int j = 0; j < 4; j++) {
                    const int d  = 4 * s - 8 + j;
                    const int C0 = s * 32 + 8 * j + 2 * tig;
                    const int h0 = C0 / FPH, h1 = (C0 + 1) / FPH;
#pragma unroll
                    for (int m = 0; m < 2; m++) {
                        const int eA = ew0 + 16 * m + gr, eB = eA + 8;
                        const float xA = xs[eA * XSTR + d], xB = xs[eB * XSTR + d];
                        pk[m][j][0] = xA * shv0[m][0] * acc[m][j][0] * al[eA * 4 + h0]
                                    + xB * shv0[m][1] * acc[m][j][2] * al[eB * 4 + h0];
                        pk[m][j][1] = xA * shv1[m][0] * acc[m][j][1] * al[eA * 4 + h1]
                                    + xB * shv1[m][1] * acc[m][j][3] * al[eB * 4 + h1];
                    }
                }
            }
#pragma unroll
            for (int m = 0; m < 2; m++)
#pragma unroll
                for (int j = 0; j < 4; j++)
#pragma unroll
                    for (int p = 0; p < 2; p++) {
                        pk[m][j][p] += __shfl_xor_sync(0xffffffffu, pk[m][j][p], 4);
                        pk[m][j][p] += __shfl_xor_sync(0xffffffffu, pk[m][j][p], 8);
                        pk[m][j][p] += __shfl_xor_sync(0xffffffffu, pk[m][j][p], 16);
                    }
            if (gr == 0) {
#pragma unroll
                for (int m = 0; m < 2; m++)
#pragma unroll
                    for (int j = 0; j < 4; j++)
                        *reinterpret_cast<float2*>(
                            g_accN + (n0 + 2 * warp + m) * FDIM + s * 32 + 8 * j + 2 * tig) =
                            make_float2(pk[m][j][0], pk[m][j][1]);
            }
        }
        __syncthreads();
    }

    // ---------- epilogue: out[n] = accN[n] @ W_out (576x64), c-split halves ----------
    {
        const int dcol = tid & 63;
        const int half = tid >> 6;
        const int cbeg = half * 288;
        const float* accN = g_accN + n0 * FDIM;
        float s[8] = {0.f, 0.f, 0.f, 0.f, 0.f, 0.f, 0.f, 0.f};
        for (int c = cbeg; c < cbeg + 288; c += 4) {
            float w0 = W_out[(c + 0) * 64 + dcol];
            float w1 = W_out[(c + 1) * 64 + dcol];
            float w2 = W_out[(c + 2) * 64 + dcol];
            float w3 = W_out[(c + 3) * 64 + dcol];
#pragma unroll
            for (int n = 0; n < 8; n++) {
                float4 a = *reinterpret_cast<const float4*>(accN + n * FDIM + c);
                s[n] += a.x * w0 + a.y * w1 + a.z * w2 + a.w * w3;
            }
        }
        float* scratch = (float*)(smu + OFF_ACT);
        if (half == 1) {
#pragma unroll
            for (int n = 0; n < 8; n++) scratch[n * 64 + dcol] = s[n];
        }
        __syncthreads();
        if (half == 0) {
#pragma unroll
            for (int n = 0; n < 8; n++)
                out[(n0 + n) * 64 + dcol] = s[n] + scratch[n * 64 + dcol];
        }
    }
}

extern "C" void kernel_launch(void* const* d_in, const int* in_sizes, int n_in,
                              void* d_out, int out_size) {
    const float* node_feat = (const float*)d_in[0];
    const float* edge_sh   = (const float*)d_in[1];
    const float* edge_inv  = (const float*)d_in[2];
    const float* cutoff    = (const float*)d_in[3];
    const float* Wk1       = (const float*)d_in[4];
    const float* Wk2       = (const float*)d_in[5];
    const float* Wk3       = (const float*)d_in[6];
    const float* Wv1       = (const float*)d_in[7];
    const float* Wv2       = (const float*)d_in[8];
    const float* Wv3       = (const float*)d_in[9];
    const float* W_logit   = (const float*)d_in[10];
    const float* W_out     = (const float*)d_in[11];
    const int*   edge_src  = (const int*)d_in[12];
    float* out = (float*)d_out;

    prep_kernel<<<(Q_TOTAL + 255) / 256, 256>>>(Wk1, Wk2, Wk3, Wv1, Wv2, Wv3);

    size_t smem = SMEM_U32 * 4;
    cudaFuncSetAttribute(fused_attn_kernel,
                         cudaFuncAttributeMaxDynamicSharedMemorySize, (int)smem);
    fused_attn_kernel<<<NNODES / GN, THREADS, smem>>>(
        node_feat, edge_sh, edge_inv, cutoff,
        W_logit, W_out, edge_src, out);
}

// round 16
// speedup vs baseline: 1.6379x; 1.6379x over previous
#include <cuda_runtime.h>
#include <cuda_fp16.h>
#include <math.h>

// Problem constants
#define KEDGE   16
#define SDIM    8
#define HHEAD   4
#define FDIM    576
#define FPH     144
#define NNODES  8192

// Tiling: 4 nodes (64 edges) per block, 4 warps, warp = 1 node = one m16 atom
#define GN      4
#define EPB     64
#define THREADS 128
#define XSTR    68    // xs row stride (f32)

// smem offsets (u32 units) — identical to R9 layout
#define OFF_ACT 0                       // 4096 u32 (16 KB): warp w -> [w*1024, w*1024+1024)
#define OFF_XS  4096                    // [64][68] f32
#define OFF_QN  (OFF_XS + EPB*XSTR)     // [4][64]
#define OFF_SH  (OFF_QN + GN*64)        // [64][8]
#define OFF_WL  (OFF_SH + EPB*SDIM)     // [128][4]
#define OFF_LG  (OFF_WL + 512)          // [64][4]
#define OFF_AL  (OFF_LG + EPB*4)        // [64][4]
#define OFF_CW  (OFF_AL + EPB*4)        // [64]
#define OFF_ACC (OFF_CW + EPB)          // [4][576]
#define SMEM_U32 (OFF_ACC + GN*FDIM)    // 12608 u32 = 50432 B -> 3 CTAs/SM

// ---- fragment-ordered packed fp16 weights (single plane), paired-j uint4 ----
// uint4 idx within a 64-col block: (jp*4 + kb)*32 + lane, jp=0..3 pairs (2jp, 2jp+1)
//   w.x = f16x2 rows (kA,kA+1) col 2jp*8+gr ; w.y = rows (kB,kB+1) same col
//   w.z / w.w = same for col (2jp+1)*8+gr ;  kA=2(kb*8+tig), kB=kA+8
#define Q_K1 0          // 64x64 -> 512 uint4 (8 KB)
#define Q_K2 512
#define Q_V1 1024
#define Q_V2 1536
#define Q_K3 2048       // 64x576 -> 4608 uint4 (9 chunks x 512)
#define Q_V3 6656
#define Q_TOTAL 11264
__device__ __align__(16) uint4 g_Wpk[Q_TOTAL];

__device__ __forceinline__ unsigned pack_f16x2(float v_odd, float v_even) {
    unsigned r;
    asm("cvt.rn.f16x2.f32 %0, %1, %2;" : "=r"(r) : "f"(v_odd), "f"(v_even));
    return r;
}
__device__ __forceinline__ float f16_lo(unsigned u) {
    __half2 h = *reinterpret_cast<__half2*>(&u);
    return __low2float(h);
}
__device__ __forceinline__ float f16_hi(unsigned u) {
    __half2 h = *reinterpret_cast<__half2*>(&u);
    return __high2float(h);
}

__device__ __forceinline__ void mma16(float c[4], const unsigned a[4],
                                      unsigned b0, unsigned b1) {
    asm("mma.sync.aligned.m16n8k16.row.col.f32.f16.f16.f32 "
        "{%0,%1,%2,%3}, {%4,%5,%6,%7}, {%8,%9}, {%0,%1,%2,%3};"
        : "+f"(c[0]), "+f"(c[1]), "+f"(c[2]), "+f"(c[3])
        : "r"(a[0]), "r"(a[1]), "r"(a[2]), "r"(a[3]), "r"(b0), "r"(b1));
}

__device__ __forceinline__ float gelu_f(float x) {
    float u = 0.7978845608028654f * (x + 0.044715f * x * x * x);
    float t;
    asm("tanh.approx.f32 %0, %1;" : "=f"(t) : "f"(u));
    return 0.5f * x * (1.0f + t);
}

__global__ void prep_kernel(const float* __restrict__ Wk1, const float* __restrict__ Wk2,
                            const float* __restrict__ Wk3, const float* __restrict__ Wv1,
                            const float* __restrict__ Wv2, const float* __restrict__ Wv3) {
    int i = blockIdx.x * 256 + threadIdx.x;
    if (i >= Q_TOTAL) return;
    const float* src; int ncols, q, colbase;
    if      (i < Q_K2) { src = Wk1; ncols = 64;  q = i - Q_K1; colbase = 0; }
    else if (i < Q_V1) { src = Wk2; ncols = 64;  q = i - Q_K2; colbase = 0; }
    else if (i < Q_V2) { src = Wv1; ncols = 64;  q = i - Q_V1; colbase = 0; }
    else if (i < Q_K3) { src = Wv2; ncols = 64;  q = i - Q_V2; colbase = 0; }
    else if (i < Q_V3) { src = Wk3; ncols = 576; q = (i - Q_K3) & 511; colbase = ((i - Q_K3) >> 9) * 64; }
    else               { src = Wv3; ncols = 576; q = (i - Q_V3) & 511; colbase = ((i - Q_V3) >> 9) * 64; }
    const int jp   = q >> 7;
    const int kb   = (q >> 5) & 3;
    const int lane = q & 31;
    const int gr   = lane >> 2;
    const int tig  = lane & 3;
    const int c0   = colbase + (2 * jp) * 8 + gr;
    const int c1   = colbase + (2 * jp + 1) * 8 + gr;
    const int kA   = 2 * (kb * 8 + tig);
    const int kB   = kA + 8;
    uint4 o;
    o.x = pack_f16x2(src[(kA + 1) * ncols + c0], src[kA * ncols + c0]);
    o.y = pack_f16x2(src[(kB + 1) * ncols + c0], src[kB * ncols + c0]);
    o.z = pack_f16x2(src[(kA + 1) * ncols + c1], src[kA * ncols + c1]);
    o.w = pack_f16x2(src[(kB + 1) * ncols + c1], src[kB * ncols + c1]);
    g_Wpk[i] = o;
}

// write one (c2) column-pair for this edge: fp16 hi + fp16 residual planes
__device__ __forceinline__ void act_store_c2(unsigned* hw, unsigned* lw,
                                             int c2, int gr_e, int gr8,
                                             float v0, float v1) {
    unsigned h = pack_f16x2(v1, v0);
    unsigned l = pack_f16x2(v1 - f16_hi(h), v0 - f16_lo(h));
    const int quad = ((c2 >> 3) * 4 + (c2 & 3)) * 8 + gr_e;
    const int idx  = quad * 4 + ((c2 >> 2) & 1) * 2 + gr8;
    hw[idx] = h;
    lw[idx] = l;
}

// 16x64x64 layer GEMM, in-place gelu+split store. actq = warp's uint4 base.
__device__ __forceinline__ void layer_gemm(uint4* actq, const uint4* __restrict__ Wq,
                                           int gr, int tig, int lane) {
    float acc[8][4];
#pragma unroll
    for (int j = 0; j < 8; j++)
#pragma unroll
        for (int p = 0; p < 4; p++) acc[j][p] = 0.f;

#pragma unroll
    for (int kb = 0; kb < 4; kb++) {
        uint4 ahq = actq[(kb * 4 + tig) * 8 + gr];
        uint4 alq = actq[128 + (kb * 4 + tig) * 8 + gr];
        unsigned Ah[4] = {ahq.x, ahq.y, ahq.z, ahq.w};
        unsigned Al[4] = {alq.x, alq.y, alq.z, alq.w};
        const uint4* wp = Wq + kb * 32 + lane;
#pragma unroll
        for (int jp = 0; jp < 4; jp++) {
            uint4 w = wp[jp * 128];
            mma16(acc[2 * jp],     Ah, w.x, w.y);
            mma16(acc[2 * jp],     Al, w.x, w.y);
            mma16(acc[2 * jp + 1], Ah, w.z, w.w);
            mma16(acc[2 * jp + 1], Al, w.z, w.w);
        }
    }
    __syncwarp();
    unsigned* hw = (unsigned*)actq;
    unsigned* lw = hw + 512;
#pragma unroll
    for (int j = 0; j < 8; j++) {
        float g0 = gelu_f(acc[j][0]), g1 = gelu_f(acc[j][1]);
        float g2 = gelu_f(acc[j][2]), g3 = gelu_f(acc[j][3]);
        unsigned hA = pack_f16x2(g1, g0);
        unsigned hB = pack_f16x2(g3, g2);
        unsigned lA = pack_f16x2(g1 - f16_hi(hA), g0 - f16_lo(hA));
        unsigned lB = pack_f16x2(g3 - f16_hi(hB), g2 - f16_lo(hB));
        const int c2   = j * 4 + tig;
        const int quad = ((c2 >> 3) * 4 + (c2 & 3)) * 8 + gr;
        const int base = quad * 4 + ((c2 >> 2) & 1) * 2;
        *reinterpret_cast<uint2*>(hw + base) = make_uint2(hA, hB);
        *reinterpret_cast<uint2*>(lw + base) = make_uint2(lA, lB);
    }
    __syncwarp();
}

// 16x64 chunk of a 64x576 layer-3 GEMM; acc left in registers.
__device__ __forceinline__ void chunk_gemm(const uint4* actq, const uint4* __restrict__ Wq,
                                           int ci, int gr, int tig, int lane,
                                           float acc[8][4]) {
#pragma unroll
    for (int j = 0; j < 8; j++)
#pragma unroll
        for (int p = 0; p < 4; p++) acc[j][p] = 0.f;

#pragma unroll
    for (int kb = 0; kb < 4; kb++) {
        uint4 ahq = actq[(kb * 4 + tig) * 8 + gr];
        uint4 alq = actq[128 + (kb * 4 + tig) * 8 + gr];
        unsigned Ah[4] = {ahq.x, ahq.y, ahq.z, ahq.w};
        unsigned Al[4] = {alq.x, alq.y, alq.z, alq.w};
        const uint4* wp = Wq + ci * 512 + kb * 32 + lane;
#pragma unroll
        for (int jp = 0; jp < 4; jp++) {
            uint4 w = wp[jp * 128];
            mma16(acc[2 * jp],     Ah, w.x, w.y);
            mma16(acc[2 * jp],     Al, w.x, w.y);
            mma16(acc[2 * jp + 1], Ah, w.z, w.w);
            mma16(acc[2 * jp + 1], Al, w.z, w.w);
        }
    }
}

__global__ __launch_bounds__(THREADS, 3)
void fused_attn_kernel(const float* __restrict__ node_feat,
                       const float* __restrict__ edge_sh,
                       const float* __restrict__ edge_inv,
                       const float* __restrict__ cutoff,
                       const float* __restrict__ W_logit,
                       const float* __restrict__ W_out,
                       const int* __restrict__ edge_src,
                       float* __restrict__ out) {
    extern __shared__ unsigned smu[];
    float* xs   = (float*)(smu + OFF_XS);
    float* qn   = (float*)(smu + OFF_QN);
    float* shm  = (float*)(smu + OFF_SH);
    float* WLs  = (float*)(smu + OFF_WL);
    float* lg   = (float*)(smu + OFF_LG);
    float* al   = (float*)(smu + OFF_AL);
    float* cw   = (float*)(smu + OFF_CW);
    float* accN = (float*)(smu + OFF_ACC);

    const int tid  = threadIdx.x;
    const int warp = tid >> 5;
    const int lane = tid & 31;
    const int gr   = lane >> 2;
    const int tig  = lane & 3;
    const int ew0  = warp * 16;
    const int n0   = blockIdx.x * GN;
    const int eg0  = blockIdx.x * EPB;

    uint4* actq = reinterpret_cast<uint4*>(smu + OFF_ACT) + warp * 256;
    unsigned* hw = smu + OFF_ACT + warp * 1024;
    unsigned* lw = hw + 512;

    // ---------- phase 0 ----------
    if (tid < EPB) cw[tid] = cutoff[eg0 + tid];
    for (int i = tid; i < 512; i += THREADS) WLs[i] = W_logit[i];
    {
        const int i2 = lane * 2;
        *reinterpret_cast<float2*>(qn + warp * 64 + i2) =
            *reinterpret_cast<const float2*>(node_feat + (n0 + warp) * 64 + i2);
    }
    {   // per-edge: 2 lanes per edge, each half the columns
        const int el   = lane >> 1;           // warp-local edge 0..15
        const int half = lane & 1;
        const int e    = ew0 + el;
        const int ge   = eg0 + e;
        const int gre  = el & 7, gr8 = el >> 3;
        *reinterpret_cast<float4*>(shm + e * 8 + half * 4) =
            *reinterpret_cast<const float4*>(edge_sh + ge * 8 + half * 4);
        const int srce = edge_src[ge];
#pragma unroll
        for (int m = 0; m < 8; m++) {
            const int c4 = half * 32 + m * 4;
            float4 v = *reinterpret_cast<const float4*>(edge_inv + ge * 64 + c4);
            act_store_c2(hw, lw, (c4 >> 1),     gre, gr8, v.x, v.y);
            act_store_c2(hw, lw, (c4 >> 1) + 1, gre, gr8, v.z, v.w);
            *reinterpret_cast<float4*>(xs + e * XSTR + c4) =
                *reinterpret_cast<const float4*>(node_feat + srce * 64 + c4);
        }
    }
    __syncthreads();

    // hoisted per-edge sh values at this thread's two columns
    const int eA = ew0 + gr, eB = ew0 + gr + 8;
    const float shvA0 = shm[eA * 8 + 2 * tig], shvA1 = shm[eA * 8 + 2 * tig + 1];
    const float shvB0 = shm[eB * 8 + 2 * tig], shvB1 = shm[eB * 8 + 2 * tig + 1];

    // ---------- key MLP layers 1,2 ----------
    layer_gemm(actq, g_Wpk + Q_K1, gr, tig, lane);
    layer_gemm(actq, g_Wpk + Q_K2, gr, tig, lane);

    // ---------- key layer-3 chunks -> logit partials ----------
    float pl[2][4];
#pragma unroll
    for (int i = 0; i < 2; i++)
#pragma unroll
        for (int h = 0; h < 4; h++) pl[i][h] = 0.f;

    const float* qrow = qn + warp * 64;

#pragma unroll 1
    for (int ci = 0; ci < 9; ci++) {
        float acc[8][4];
        chunk_gemm(actq, g_Wpk + Q_K3, ci, gr, tig, lane, acc);

        if (ci == 0) {
#pragma unroll
            for (int j = 0; j < 8; j++) {
                const int t0 = 8 * j + 2 * tig;
                float4 wl0 = *reinterpret_cast<const float4*>(WLs + t0 * 4);
                float4 wl1 = *reinterpret_cast<const float4*>(WLs + t0 * 4 + 4);
                const float q0 = qrow[t0], q1 = qrow[t0 + 1];
                float cA0 = q0 * xs[eA * XSTR + t0]     * acc[j][0];
                float cA1 = q1 * xs[eA * XSTR + t0 + 1] * acc[j][1];
                float cB0 = q0 * xs[eB * XSTR + t0]     * acc[j][2];
                float cB1 = q1 * xs[eB * XSTR + t0 + 1] * acc[j][3];
                pl[0][0] += cA0 * wl0.x + cA1 * wl1.x;
                pl[0][1] += cA0 * wl0.y + cA1 * wl1.y;
                pl[0][2] += cA0 * wl0.z + cA1 * wl1.z;
                pl[0][3] += cA0 * wl0.w + cA1 * wl1.w;
                pl[1][0] += cB0 * wl0.x + cB1 * wl1.x;
                pl[1][1] += cB0 * wl0.y + cB1 * wl1.y;
                pl[1][2] += cB0 * wl0.z + cB1 * wl1.z;
                pl[1][3] += cB0 * wl0.w + cB1 * wl1.w;
            }
        } else {
#pragma unroll
            for (int j = 0; j < 8; j++) {
                const int d = 8 * (ci - 1) + j;
                float4 wl = *reinterpret_cast<const float4*>(WLs + (64 + d) * 4);
                const float qd = qrow[d];
                float cA = qd * xs[eA * XSTR + d] *
                           (shvA0 * shvA0 * acc[j][0] + shvA1 * shvA1 * acc[j][1]);
                float cB = qd * xs[eB * XSTR + d] *
                           (shvB0 * shvB0 * acc[j][2] + shvB1 * shvB1 * acc[j][3]);
                pl[0][0] += cA * wl.x; pl[0][1] += cA * wl.y;
                pl[0][2] += cA * wl.z; pl[0][3] += cA * wl.w;
                pl[1][0] += cB * wl.x; pl[1][1] += cB * wl.y;
                pl[1][2] += cB * wl.z; pl[1][3] += cB * wl.w;
            }
        }
    }

    // reduce pl over the 4 tig lanes; tig==0 stores
#pragma unroll
    for (int msk = 1; msk < 4; msk <<= 1)
#pragma unroll
        for (int i = 0; i < 2; i++)
#pragma unroll
            for (int h = 0; h < 4; h++)
                pl[i][h] += __shfl_xor_sync(0xffffffffu, pl[i][h], msk);
    if (tig == 0) {
        *reinterpret_cast<float4*>(lg + eA * 4) =
            make_float4(pl[0][0], pl[0][1], pl[0][2], pl[0][3]);
        *reinterpret_cast<float4*>(lg + eB * 4) =
            make_float4(pl[1][0], pl[1][1], pl[1][2], pl[1][3]);
    }
    __syncwarp();

    // reload edge_inv split (warp-local rows)
    {
        const int el   = lane >> 1;
        const int half = lane & 1;
        const int ge   = eg0 + ew0 + el;
        const int gre  = el & 7, gr8 = el >> 3;
#pragma unroll
        for (int m = 0; m < 8; m++) {
            const int c4 = half * 32 + m * 4;
            float4 v = *reinterpret_cast<const float4*>(edge_inv + ge * 64 + c4);
            act_store_c2(hw, lw, (c4 >> 1),     gre, gr8, v.x, v.y);
            act_store_c2(hw, lw, (c4 >> 1) + 1, gre, gr8, v.z, v.w);
        }
    }
    __syncthreads();   // lg visible to warp 0

    // ---------- softmax ----------
    if (tid < GN * HHEAD) {
        const int n = tid >> 2, h = tid & 3;
        float mx = -3.0e38f;
        for (int j = 0; j < KEDGE; j++)
            mx = fmaxf(mx, lg[(n * KEDGE + j) * 4 + h]);
        float z = 0.f;
        float ex[KEDGE];
        for (int j = 0; j < KEDGE; j++) {
            const int e = n * KEDGE + j;
            ex[j] = cw[e] * expf(lg[e * 4 + h] - mx);
            z += ex[j];
        }
        if (z == 0.f) z = 1.f;
        const float inv = 1.f / z;
        for (int j = 0; j < KEDGE; j++)
            al[(n * KEDGE + j) * 4 + h] = sqrtf(ex[j] * inv);
    }

    // ---------- value MLP layers 1,2 (independent of al) ----------
    layer_gemm(actq, g_Wpk + Q_V1, gr, tig, lane);
    layer_gemm(actq, g_Wpk + Q_V2, gr, tig, lane);
    __syncthreads();   // al visible

    // ---------- value layer-3 chunks -> node accumulators ----------
#pragma unroll 1
    for (int ci = 0; ci < 9; ci++) {
        float acc[8][4];
        chunk_gemm(actq, g_Wpk + Q_V3, ci, gr, tig, lane, acc);

        float pk[8][2];
        if (ci == 0) {
            const float aA = al[eA * 4], aB = al[eB * 4];
#pragma unroll
            for (int j = 0; j < 8; j++) {
                const int t0 = 8 * j + 2 * tig;
                pk[j][0] = xs[eA * XSTR + t0]     * acc[j][0] * aA
                         + xs[eB * XSTR + t0]     * acc[j][2] * aB;
                pk[j][1] = xs[eA * XSTR + t0 + 1] * acc[j][1] * aA
                         + xs[eB * XSTR + t0 + 1] * acc[j][3] * aB;
            }
        } else {
#pragma unroll
            for (int j = 0; j < 8; j++) {
                const int d  = 8 * (ci - 1) + j;
                const int C0 = ci * 64 + 8 * j + 2 * tig;
                const int h0 = C0 / FPH, h1 = (C0 + 1) / FPH;
                const float xA = xs[eA * XSTR + d], xB = xs[eB * XSTR + d];
                pk[j][0] = xA * shvA0 * acc[j][0] * al[eA * 4 + h0]
                         + xB * shvB0 * acc[j][2] * al[eB * 4 + h0];
                pk[j][1] = xA * shvA1 * acc[j][1] * al[eA * 4 + h1]
                         + xB * shvB1 * acc[j][3] * al[eB * 4 + h1];
            }
        }
#pragma unroll
        for (int j = 0; j < 8; j++)
#pragma unroll
            for (int p = 0; p < 2; p++) {
                pk[j][p] += __shfl_xor_sync(0xffffffffu, pk[j][p], 4);
                pk[j][p] += __shfl_xor_sync(0xffffffffu, pk[j][p], 8);
                pk[j][p] += __shfl_xor_sync(0xffffffffu, pk[j][p], 16);
            }
        if (gr == 0) {
#pragma unroll
            for (int j = 0; j < 8; j++)
                *reinterpret_cast<float2*>(accN + warp * FDIM + ci * 64 + 8 * j + 2 * tig) =
                    make_float2(pk[j][0], pk[j][1]);
        }
    }
    __syncthreads();   // accN complete; act region free as scratch

    // ---------- epilogue: out[n] = accN[n] @ W_out (576x64), c-split halves ----------
    {
        const int dcol = tid & 63;
        const int half = tid >> 6;
        const int cbeg = half * 288;
        float s[4] = {0.f, 0.f, 0.f, 0.f};
        for (int c = cbeg; c < cbeg + 288; c += 4) {
            float w0 = W_out[(c + 0) * 64 + dcol];
            float w1 = W_out[(c + 1) * 64 + dcol];
            float w2 = W_out[(c + 2) * 64 + dcol];
            float w3 = W_out[(c + 3) * 64 + dcol];
#pragma unroll
            for (int n = 0; n < 4; n++) {
                float4 a = *reinterpret_cast<const float4*>(accN + n * FDIM + c);
                s[n] += a.x * w0 + a.y * w1 + a.z * w2 + a.w * w3;
            }
        }
        float* scratch = (float*)(smu + OFF_ACT);
        if (half == 1) {
#pragma unroll
            for (int n = 0; n < 4; n++) scratch[n * 64 + dcol] = s[n];
        }
        __syncthreads();
        if (half == 0) {
#pragma unroll
            for (int n = 0; n < 4; n++)
                out[(n0 + n) * 64 + dcol] = s[n] + scratch[n * 64 + dcol];
        }
    }
}

extern "C" void kernel_launch(void* const* d_in, const int* in_sizes, int n_in,
                              void* d_out, int out_size) {
    const float* node_feat = (const float*)d_in[0];
    const float* edge_sh   = (const float*)d_in[1];
    const float* edge_inv  = (const float*)d_in[2];
    const float* cutoff    = (const float*)d_in[3];
    const float* Wk1       = (const float*)d_in[4];
    const float* Wk2       = (const float*)d_in[5];
    const float* Wk3       = (const float*)d_in[6];
    const float* Wv1       = (const float*)d_in[7];
    const float* Wv2       = (const float*)d_in[8];
    const float* Wv3       = (const float*)d_in[9];
    const float* W_logit   = (const float*)d_in[10];
    const float* W_out     = (const float*)d_in[11];
    const int*   edge_src  = (const int*)d_in[12];
    float* out = (float*)d_out;

    prep_kernel<<<(Q_TOTAL + 255) / 256, 256>>>(Wk1, Wk2, Wk3, Wv1, Wv2, Wv3);

    size_t smem = SMEM_U32 * 4;
    cudaFuncSetAttribute(fused_attn_kernel,
                         cudaFuncAttributeMaxDynamicSharedMemorySize, (int)smem);
    fused_attn_kernel<<<NNODES / GN, THREADS, smem>>>(
        node_feat, edge_sh, edge_inv, cutoff,
        W_logit, W_out, edge_src, out);
}

// round 17
// speedup vs baseline: 1.7284x; 1.0553x over previous
#include <cuda_runtime.h>
#include <cuda_fp16.h>
#include <math.h>

// Problem constants
#define KEDGE   16
#define SDIM    8
#define HHEAD   4
#define FDIM    576
#define FPH     144
#define NNODES  8192

// Tiling: 4 nodes (64 edges) per block, 4 warps, warp = 1 node = one m16 atom
#define GN      4
#define EPB     64
#define THREADS 128
#define XSTR    68    // xs row stride (f32)

// smem offsets (u32 units)
#define OFF_ACT 0                       // 4096 u32 (16 KB): warp w -> [w*1024, w*1024+1024)
#define OFF_XS  4096                    // [64][68] f32
#define OFF_QN  (OFF_XS + EPB*XSTR)     // [4][64]
#define OFF_SH  (OFF_QN + GN*64)        // [64][8]
#define OFF_WL  (OFF_SH + EPB*SDIM)     // [128][4]
#define OFF_LG  (OFF_WL + 512)          // [64][4]
#define OFF_AL  (OFF_LG + EPB*4)        // [64][4]
#define OFF_CW  (OFF_AL + EPB*4)        // [64]
#define OFF_ACC (OFF_CW + EPB)          // [4][576]
#define SMEM_U32 (OFF_ACC + GN*FDIM)    // 12608 u32 = 50432 B -> 3 CTAs/SM

// ---- fragment-ordered packed fp16 weights (single plane), paired-j uint4 ----
#define Q_K1 0          // 64x64 -> 512 uint4
#define Q_K2 512
#define Q_V1 1024
#define Q_V2 1536
#define Q_K3 2048       // 64x576 -> 4608 uint4 (9 chunks x 512)
#define Q_V3 6656
#define Q_TOTAL 11264
__device__ __align__(16) uint4 g_Wpk[Q_TOTAL];

__device__ __forceinline__ unsigned pack_f16x2(float v_odd, float v_even) {
    unsigned r;
    asm("cvt.rn.f16x2.f32 %0, %1, %2;" : "=r"(r) : "f"(v_odd), "f"(v_even));
    return r;
}
__device__ __forceinline__ float f16_lo(unsigned u) {
    __half2 h = *reinterpret_cast<__half2*>(&u);
    return __low2float(h);
}
__device__ __forceinline__ float f16_hi(unsigned u) {
    __half2 h = *reinterpret_cast<__half2*>(&u);
    return __high2float(h);
}

__device__ __forceinline__ void mma16(float c[4], const unsigned a[4],
                                      unsigned b0, unsigned b1) {
    asm("mma.sync.aligned.m16n8k16.row.col.f32.f16.f16.f32 "
        "{%0,%1,%2,%3}, {%4,%5,%6,%7}, {%8,%9}, {%0,%1,%2,%3};"
        : "+f"(c[0]), "+f"(c[1]), "+f"(c[2]), "+f"(c[3])
        : "r"(a[0]), "r"(a[1]), "r"(a[2]), "r"(a[3]), "r"(b0), "r"(b1));
}

__device__ __forceinline__ float gelu_f(float x) {
    float u = 0.7978845608028654f * (x + 0.044715f * x * x * x);
    float t;
    asm("tanh.approx.f32 %0, %1;" : "=f"(t) : "f"(u));
    return 0.5f * x * (1.0f + t);
}

__global__ void prep_kernel(const float* __restrict__ Wk1, const float* __restrict__ Wk2,
                            const float* __restrict__ Wk3, const float* __restrict__ Wv1,
                            const float* __restrict__ Wv2, const float* __restrict__ Wv3) {
    int i = blockIdx.x * 256 + threadIdx.x;
    if (i >= Q_TOTAL) return;
    const float* src; int ncols, q, colbase;
    if      (i < Q_K2) { src = Wk1; ncols = 64;  q = i - Q_K1; colbase = 0; }
    else if (i < Q_V1) { src = Wk2; ncols = 64;  q = i - Q_K2; colbase = 0; }
    else if (i < Q_V2) { src = Wv1; ncols = 64;  q = i - Q_V1; colbase = 0; }
    else if (i < Q_K3) { src = Wv2; ncols = 64;  q = i - Q_V2; colbase = 0; }
    else if (i < Q_V3) { src = Wk3; ncols = 576; q = (i - Q_K3) & 511; colbase = ((i - Q_K3) >> 9) * 64; }
    else               { src = Wv3; ncols = 576; q = (i - Q_V3) & 511; colbase = ((i - Q_V3) >> 9) * 64; }
    const int jp   = q >> 7;
    const int kb   = (q >> 5) & 3;
    const int lane = q & 31;
    const int gr   = lane >> 2;
    const int tig  = lane & 3;
    const int c0   = colbase + (2 * jp) * 8 + gr;
    const int c1   = colbase + (2 * jp + 1) * 8 + gr;
    const int kA   = 2 * (kb * 8 + tig);
    const int kB   = kA + 8;
    uint4 o;
    o.x = pack_f16x2(src[(kA + 1) * ncols + c0], src[kA * ncols + c0]);
    o.y = pack_f16x2(src[(kB + 1) * ncols + c0], src[kB * ncols + c0]);
    o.z = pack_f16x2(src[(kA + 1) * ncols + c1], src[kA * ncols + c1]);
    o.w = pack_f16x2(src[(kB + 1) * ncols + c1], src[kB * ncols + c1]);
    g_Wpk[i] = o;
}

// write one (c2) column-pair for this edge: fp16 hi + fp16 residual planes
__device__ __forceinline__ void act_store_c2(unsigned* hw, unsigned* lw,
                                             int c2, int gr_e, int gr8,
                                             float v0, float v1) {
    unsigned h = pack_f16x2(v1, v0);
    unsigned l = pack_f16x2(v1 - f16_hi(h), v0 - f16_lo(h));
    const int quad = ((c2 >> 3) * 4 + (c2 & 3)) * 8 + gr_e;
    const int idx  = quad * 4 + ((c2 >> 2) & 1) * 2 + gr8;
    hw[idx] = h;
    lw[idx] = l;
}

// 16x64x64 layer GEMM (2-term A), in-place gelu+split store.
__device__ __forceinline__ void layer_gemm(uint4* actq, const uint4* __restrict__ Wq,
                                           int gr, int tig, int lane) {
    float acc[8][4];
#pragma unroll
    for (int j = 0; j < 8; j++)
#pragma unroll
        for (int p = 0; p < 4; p++) acc[j][p] = 0.f;

#pragma unroll
    for (int kb = 0; kb < 4; kb++) {
        uint4 ahq = actq[(kb * 4 + tig) * 8 + gr];
        uint4 alq = actq[128 + (kb * 4 + tig) * 8 + gr];
        unsigned Ah[4] = {ahq.x, ahq.y, ahq.z, ahq.w};
        unsigned Al[4] = {alq.x, alq.y, alq.z, alq.w};
        const uint4* wp = Wq + kb * 32 + lane;
#pragma unroll
        for (int jp = 0; jp < 4; jp++) {
            uint4 w = wp[jp * 128];
            mma16(acc[2 * jp],     Ah, w.x, w.y);
            mma16(acc[2 * jp],     Al, w.x, w.y);
            mma16(acc[2 * jp + 1], Ah, w.z, w.w);
            mma16(acc[2 * jp + 1], Al, w.z, w.w);
        }
    }
    __syncwarp();
    unsigned* hw = (unsigned*)actq;
    unsigned* lw = hw + 512;
#pragma unroll
    for (int j = 0; j < 8; j++) {
        float g0 = gelu_f(acc[j][0]), g1 = gelu_f(acc[j][1]);
        float g2 = gelu_f(acc[j][2]), g3 = gelu_f(acc[j][3]);
        unsigned hA = pack_f16x2(g1, g0);
        unsigned hB = pack_f16x2(g3, g2);
        unsigned lA = pack_f16x2(g1 - f16_hi(hA), g0 - f16_lo(hA));
        unsigned lB = pack_f16x2(g3 - f16_hi(hB), g2 - f16_lo(hB));
        const int c2   = j * 4 + tig;
        const int quad = ((c2 >> 3) * 4 + (c2 & 3)) * 8 + gr;
        const int base = quad * 4 + ((c2 >> 2) & 1) * 2;
        *reinterpret_cast<uint2*>(hw + base) = make_uint2(hA, hB);
        *reinterpret_cast<uint2*>(lw + base) = make_uint2(lA, lB);
    }
    __syncwarp();
}

// 16x64 chunk GEMM, 2-term A (key path): acc left in registers.
__device__ __forceinline__ void chunk_gemm2(const uint4* actq, const uint4* __restrict__ Wq,
                                            int ci, int gr, int tig, int lane,
                                            float acc[8][4]) {
#pragma unroll
    for (int j = 0; j < 8; j++)
#pragma unroll
        for (int p = 0; p < 4; p++) acc[j][p] = 0.f;

#pragma unroll
    for (int kb = 0; kb < 4; kb++) {
        uint4 ahq = actq[(kb * 4 + tig) * 8 + gr];
        uint4 alq = actq[128 + (kb * 4 + tig) * 8 + gr];
        unsigned Ah[4] = {ahq.x, ahq.y, ahq.z, ahq.w};
        unsigned Al[4] = {alq.x, alq.y, alq.z, alq.w};
        const uint4* wp = Wq + ci * 512 + kb * 32 + lane;
#pragma unroll
        for (int jp = 0; jp < 4; jp++) {
            uint4 w = wp[jp * 128];
            mma16(acc[2 * jp],     Ah, w.x, w.y);
            mma16(acc[2 * jp],     Al, w.x, w.y);
            mma16(acc[2 * jp + 1], Ah, w.z, w.w);
            mma16(acc[2 * jp + 1], Al, w.z, w.w);
        }
    }
}

// 16x64 chunk GEMM, 1-term A (value path, linear error): half the mmas, no Al loads.
__device__ __forceinline__ void chunk_gemm1(const uint4* actq, const uint4* __restrict__ Wq,
                                            int ci, int gr, int tig, int lane,
                                            float acc[8][4]) {
#pragma unroll
    for (int j = 0; j < 8; j++)
#pragma unroll
        for (int p = 0; p < 4; p++) acc[j][p] = 0.f;

#pragma unroll
    for (int kb = 0; kb < 4; kb++) {
        uint4 ahq = actq[(kb * 4 + tig) * 8 + gr];
        unsigned Ah[4] = {ahq.x, ahq.y, ahq.z, ahq.w};
        const uint4* wp = Wq + ci * 512 + kb * 32 + lane;
#pragma unroll
        for (int jp = 0; jp < 4; jp++) {
            uint4 w = wp[jp * 128];
            mma16(acc[2 * jp],     Ah, w.x, w.y);
            mma16(acc[2 * jp + 1], Ah, w.z, w.w);
        }
    }
}

__global__ __launch_bounds__(THREADS, 3)
void fused_attn_kernel(const float* __restrict__ node_feat,
                       const float* __restrict__ edge_sh,
                       const float* __restrict__ edge_inv,
                       const float* __restrict__ cutoff,
                       const float* __restrict__ W_logit,
                       const float* __restrict__ W_out,
                       const int* __restrict__ edge_src,
                       float* __restrict__ out) {
    extern __shared__ unsigned smu[];
    float* xs   = (float*)(smu + OFF_XS);
    float* qn   = (float*)(smu + OFF_QN);
    float* shm  = (float*)(smu + OFF_SH);
    float* WLs  = (float*)(smu + OFF_WL);
    float* lg   = (float*)(smu + OFF_LG);
    float* al   = (float*)(smu + OFF_AL);
    float* cw   = (float*)(smu + OFF_CW);
    float* accN = (float*)(smu + OFF_ACC);

    const int tid  = threadIdx.x;
    const int warp = tid >> 5;
    const int lane = tid & 31;
    const int gr   = lane >> 2;
    const int tig  = lane & 3;
    const int ew0  = warp * 16;
    const int n0   = blockIdx.x * GN;
    const int eg0  = blockIdx.x * EPB;

    uint4* actq = reinterpret_cast<uint4*>(smu + OFF_ACT) + warp * 256;
    unsigned* hw = smu + OFF_ACT + warp * 1024;
    unsigned* lw = hw + 512;

    // ---------- phase 0 ----------
    if (tid < EPB) cw[tid] = cutoff[eg0 + tid];
    for (int i = tid; i < 512; i += THREADS) WLs[i] = W_logit[i];
    {
        const int i2 = lane * 2;
        *reinterpret_cast<float2*>(qn + warp * 64 + i2) =
            *reinterpret_cast<const float2*>(node_feat + (n0 + warp) * 64 + i2);
    }
    {   // per-edge: 2 lanes per edge, each half the columns
        const int el   = lane >> 1;
        const int half = lane & 1;
        const int e    = ew0 + el;
        const int ge   = eg0 + e;
        const int gre  = el & 7, gr8 = el >> 3;
        *reinterpret_cast<float4*>(shm + e * 8 + half * 4) =
            *reinterpret_cast<const float4*>(edge_sh + ge * 8 + half * 4);
        const int srce = edge_src[ge];
#pragma unroll
        for (int m = 0; m < 8; m++) {
            const int c4 = half * 32 + m * 4;
            float4 v = *reinterpret_cast<const float4*>(edge_inv + ge * 64 + c4);
            act_store_c2(hw, lw, (c4 >> 1),     gre, gr8, v.x, v.y);
            act_store_c2(hw, lw, (c4 >> 1) + 1, gre, gr8, v.z, v.w);
            *reinterpret_cast<float4*>(xs + e * XSTR + c4) =
                *reinterpret_cast<const float4*>(node_feat + srce * 64 + c4);
        }
    }
    __syncthreads();

    // hoisted per-edge sh values at this thread's two columns
    const int eA = ew0 + gr, eB = ew0 + gr + 8;
    const float shvA0 = shm[eA * 8 + 2 * tig], shvA1 = shm[eA * 8 + 2 * tig + 1];
    const float shvB0 = shm[eB * 8 + 2 * tig], shvB1 = shm[eB * 8 + 2 * tig + 1];

    // ---------- key MLP layers 1,2 ----------
    layer_gemm(actq, g_Wpk + Q_K1, gr, tig, lane);
    layer_gemm(actq, g_Wpk + Q_K2, gr, tig, lane);

    // ---------- key layer-3 chunks (2-term) -> logit partials ----------
    float pl[2][4];
#pragma unroll
    for (int i = 0; i < 2; i++)
#pragma unroll
        for (int h = 0; h < 4; h++) pl[i][h] = 0.f;

    const float* qrow = qn + warp * 64;

#pragma unroll 1
    for (int ci = 0; ci < 9; ci++) {
        float acc[8][4];
        chunk_gemm2(actq, g_Wpk + Q_K3, ci, gr, tig, lane, acc);

        if (ci == 0) {
#pragma unroll
            for (int j = 0; j < 8; j++) {
                const int t0 = 8 * j + 2 * tig;
                float4 wl0 = *reinterpret_cast<const float4*>(WLs + t0 * 4);
                float4 wl1 = *reinterpret_cast<const float4*>(WLs + t0 * 4 + 4);
                const float q0 = qrow[t0], q1 = qrow[t0 + 1];
                float cA0 = q0 * xs[eA * XSTR + t0]     * acc[j][0];
                float cA1 = q1 * xs[eA * XSTR + t0 + 1] * acc[j][1];
                float cB0 = q0 * xs[eB * XSTR + t0]     * acc[j][2];
                float cB1 = q1 * xs[eB * XSTR + t0 + 1] * acc[j][3];
                pl[0][0] += cA0 * wl0.x + cA1 * wl1.x;
                pl[0][1] += cA0 * wl0.y + cA1 * wl1.y;
                pl[0][2] += cA0 * wl0.z + cA1 * wl1.z;
                pl[0][3] += cA0 * wl0.w + cA1 * wl1.w;
                pl[1][0] += cB0 * wl0.x + cB1 * wl1.x;
                pl[1][1] += cB0 * wl0.y + cB1 * wl1.y;
                pl[1][2] += cB0 * wl0.z + cB1 * wl1.z;
                pl[1][3] += cB0 * wl0.w + cB1 * wl1.w;
            }
        } else {
#pragma unroll
            for (int j = 0; j < 8; j++) {
                const int d = 8 * (ci - 1) + j;
                float4 wl = *reinterpret_cast<const float4*>(WLs + (64 + d) * 4);
                const float qd = qrow[d];
                float cA = qd * xs[eA * XSTR + d] *
                           (shvA0 * shvA0 * acc[j][0] + shvA1 * shvA1 * acc[j][1]);
                float cB = qd * xs[eB * XSTR + d] *
                           (shvB0 * shvB0 * acc[j][2] + shvB1 * shvB1 * acc[j][3]);
                pl[0][0] += cA * wl.x; pl[0][1] += cA * wl.y;
                pl[0][2] += cA * wl.z; pl[0][3] += cA * wl.w;
                pl[1][0] += cB * wl.x; pl[1][1] += cB * wl.y;
                pl[1][2] += cB * wl.z; pl[1][3] += cB * wl.w;
            }
        }
    }

    // reduce pl over the 4 tig lanes; tig==0 stores
#pragma unroll
    for (int msk = 1; msk < 4; msk <<= 1)
#pragma unroll
        for (int i = 0; i < 2; i++)
#pragma unroll
            for (int h = 0; h < 4; h++)
                pl[i][h] += __shfl_xor_sync(0xffffffffu, pl[i][h], msk);
    if (tig == 0) {
        *reinterpret_cast<float4*>(lg + eA * 4) =
            make_float4(pl[0][0], pl[0][1], pl[0][2], pl[0][3]);
        *reinterpret_cast<float4*>(lg + eB * 4) =
            make_float4(pl[1][0], pl[1][1], pl[1][2], pl[1][3]);
    }
    __syncwarp();

    // reload edge_inv split (warp-local rows)
    {
        const int el   = lane >> 1;
        const int half = lane & 1;
        const int ge   = eg0 + ew0 + el;
        const int gre  = el & 7, gr8 = el >> 3;
#pragma unroll
        for (int m = 0; m < 8; m++) {
            const int c4 = half * 32 + m * 4;
            float4 v = *reinterpret_cast<const float4*>(edge_inv + ge * 64 + c4);
            act_store_c2(hw, lw, (c4 >> 1),     gre, gr8, v.x, v.y);
            act_store_c2(hw, lw, (c4 >> 1) + 1, gre, gr8, v.z, v.w);
        }
    }
    __syncthreads();   // lg visible to warp 0

    // ---------- softmax ----------
    if (tid < GN * HHEAD) {
        const int n = tid >> 2, h = tid & 3;
        float mx = -3.0e38f;
        for (int j = 0; j < KEDGE; j++)
            mx = fmaxf(mx, lg[(n * KEDGE + j) * 4 + h]);
        float z = 0.f;
        float ex[KEDGE];
        for (int j = 0; j < KEDGE; j++) {
            const int e = n * KEDGE + j;
            ex[j] = cw[e] * expf(lg[e * 4 + h] - mx);
            z += ex[j];
        }
        if (z == 0.f) z = 1.f;
        const float inv = 1.f / z;
        for (int j = 0; j < KEDGE; j++)
            al[(n * KEDGE + j) * 4 + h] = sqrtf(ex[j] * inv);
    }

    // ---------- value MLP layers 1,2 (2-term; error compounds through gelu) ----------
    layer_gemm(actq, g_Wpk + Q_V1, gr, tig, lane);
    layer_gemm(actq, g_Wpk + Q_V2, gr, tig, lane);
    __syncthreads();   // al visible

    // ---------- value layer-3 chunks (1-term; linear into output) ----------
#pragma unroll 1
    for (int ci = 0; ci < 9; ci++) {
        float acc[8][4];
        chunk_gemm1(actq, g_Wpk + Q_V3, ci, gr, tig, lane, acc);

        float pk[8][2];
        if (ci == 0) {
            const float aA = al[eA * 4], aB = al[eB * 4];
#pragma unroll
            for (int j = 0; j < 8; j++) {
                const int t0 = 8 * j + 2 * tig;
                pk[j][0] = xs[eA * XSTR + t0]     * acc[j][0] * aA
                         + xs[eB * XSTR + t0]     * acc[j][2] * aB;
                pk[j][1] = xs[eA * XSTR + t0 + 1] * acc[j][1] * aA
                         + xs[eB * XSTR + t0 + 1] * acc[j][3] * aB;
            }
        } else {
#pragma unroll
            for (int j = 0; j < 8; j++) {
                const int d  = 8 * (ci - 1) + j;
                const int C0 = ci * 64 + 8 * j + 2 * tig;
                const int h0 = C0 / FPH, h1 = (C0 + 1) / FPH;
                const float xA = xs[eA * XSTR + d], xB = xs[eB * XSTR + d];
                pk[j][0] = xA * shvA0 * acc[j][0] * al[eA * 4 + h0]
                         + xB * shvB0 * acc[j][2] * al[eB * 4 + h0];
                pk[j][1] = xA * shvA1 * acc[j][1] * al[eA * 4 + h1]
                         + xB * shvB1 * acc[j][3] * al[eB * 4 + h1];
            }
        }
#pragma unroll
        for (int j = 0; j < 8; j++)
#pragma unroll
            for (int p = 0; p < 2; p++) {
                pk[j][p] += __shfl_xor_sync(0xffffffffu, pk[j][p], 4);
                pk[j][p] += __shfl_xor_sync(0xffffffffu, pk[j][p], 8);
                pk[j][p] += __shfl_xor_sync(0xffffffffu, pk[j][p], 16);
            }
        if (gr == 0) {
#pragma unroll
            for (int j = 0; j < 8; j++)
                *reinterpret_cast<float2*>(accN + warp * FDIM + ci * 64 + 8 * j + 2 * tig) =
                    make_float2(pk[j][0], pk[j][1]);
        }
    }
    __syncthreads();   // accN complete; act region free as scratch

    // ---------- epilogue: out[n] = accN[n] @ W_out (576x64), c-split halves ----------
    {
        const int dcol = tid & 63;
        const int half = tid >> 6;
        const int cbeg = half * 288;
        float s[4] = {0.f, 0.f, 0.f, 0.f};
        for (int c = cbeg; c < cbeg + 288; c += 4) {
            float w0 = W_out[(c + 0) * 64 + dcol];
            float w1 = W_out[(c + 1) * 64 + dcol];
            float w2 = W_out[(c + 2) * 64 + dcol];
            float w3 = W_out[(c + 3) * 64 + dcol];
#pragma unroll
            for (int n = 0; n < 4; n++) {
                float4 a = *reinterpret_cast<const float4*>(accN + n * FDIM + c);
                s[n] += a.x * w0 + a.y * w1 + a.z * w2 + a.w * w3;
            }
        }
        float* scratch = (float*)(smu + OFF_ACT);
        if (half == 1) {
#pragma unroll
            for (int n = 0; n < 4; n++) scratch[n * 64 + dcol] = s[n];
        }
        __syncthreads();
        if (half == 0) {
#pragma unroll
            for (int n = 0; n < 4; n++)
                out[(n0 + n) * 64 + dcol] = s[n] + scratch[n * 64 + dcol];
        }
    }
}

extern "C" void kernel_launch(void* const* d_in, const int* in_sizes, int n_in,
                              void* d_out, int out_size) {
    const float* node_feat = (const float*)d_in[0];
    const float* edge_sh   = (const float*)d_in[1];
    const float* edge_inv  = (const float*)d_in[2];
    const float* cutoff    = (const float*)d_in[3];
    const float* Wk1       = (const float*)d_in[4];
    const float* Wk2       = (const float*)d_in[5];
    const float* Wk3       = (const float*)d_in[6];
    const float* Wv1       = (const float*)d_in[7];
    const float* Wv2       = (const float*)d_in[8];
    const float* Wv3       = (const float*)d_in[9];
    const float* W_logit   = (const float*)d_in[10];
    const float* W_out     = (const float*)d_in[11];
    const int*   edge_src  = (const int*)d_in[12];
    float* out = (float*)d_out;

    prep_kernel<<<(Q_TOTAL + 255) / 256, 256>>>(Wk1, Wk2, Wk3, Wv1, Wv2, Wv3);

    size_t smem = SMEM_U32 * 4;
    cudaFuncSetAttribute(fused_attn_kernel,
                         cudaFuncAttributeMaxDynamicSharedMemorySize, (int)smem);
    fused_attn_kernel<<<NNODES / GN, THREADS, smem>>>(
        node_feat, edge_sh, edge_inv, cutoff,
        W_logit, W_out, edge_src, out);
}